// round 1
// baseline (speedup 1.0000x reference)
#include <cuda_runtime.h>
#include <cuda_bf16.h>

// DCN-v1 cross network, fully fused:
//   x0 = input
//   for l in 0..5:  s = dot(x, W[l]);  x = input * s + x + b[l]
//   out = x
//
// B=16384 rows, D=1024, L=6.
// One warp per row. Row (1024 floats) lives in registers as 8 x float4 per
// thread (lane-coalesced: float4 index = j*32 + lane). W and b are staged in
// shared memory (48 KB) once per block. Only HBM traffic: input read once,
// output written once (128 MB total).

#define CN_D       1024
#define CN_L       6
#define CN_F4      256              // float4 per row
#define CN_WARPS   8                // rows per block
#define CN_THREADS (CN_WARPS * 32)

__global__ __launch_bounds__(CN_THREADS, 2)
void cross_network_kernel(const float* __restrict__ inp,
                          const float* __restrict__ W,
                          const float* __restrict__ bias,
                          float* __restrict__ out)
{
    __shared__ float4 sW[CN_L * CN_F4];   // 6*1024 floats = 24 KB
    __shared__ float4 sB[CN_L * CN_F4];   // 24 KB

    const int tid = threadIdx.x;

    // Stage W and b into shared (coalesced float4 loads).
    const float4* gW = (const float4*)W;
    const float4* gB = (const float4*)bias;
    #pragma unroll
    for (int i = 0; i < (CN_L * CN_F4) / CN_THREADS; ++i) {
        int idx = tid + i * CN_THREADS;
        sW[idx] = gW[idx];
        sB[idx] = gB[idx];
    }
    __syncthreads();

    const int warp = tid >> 5;
    const int lane = tid & 31;
    const size_t row = (size_t)blockIdx.x * CN_WARPS + warp;

    const float4* __restrict__ rin = (const float4*)(inp + row * CN_D);
    float4* __restrict__ rout      = (float4*)(out + row * CN_D);

    // Load the row once; keep both the original input and the running x.
    float4 in4[8], x[8];
    #pragma unroll
    for (int j = 0; j < 8; ++j) {
        in4[j] = rin[j * 32 + lane];
        x[j]   = in4[j];
    }

    #pragma unroll
    for (int l = 0; l < CN_L; ++l) {
        // s = dot(x, W[l]) : per-thread partial over 32 elements, then warp reduce.
        float s = 0.0f;
        #pragma unroll
        for (int j = 0; j < 8; ++j) {
            float4 w = sW[l * CN_F4 + j * 32 + lane];
            s = fmaf(x[j].x, w.x, s);
            s = fmaf(x[j].y, w.y, s);
            s = fmaf(x[j].z, w.z, s);
            s = fmaf(x[j].w, w.w, s);
        }
        s += __shfl_xor_sync(0xFFFFFFFFu, s, 16);
        s += __shfl_xor_sync(0xFFFFFFFFu, s, 8);
        s += __shfl_xor_sync(0xFFFFFFFFu, s, 4);
        s += __shfl_xor_sync(0xFFFFFFFFu, s, 2);
        s += __shfl_xor_sync(0xFFFFFFFFu, s, 1);

        // x = input * s + x + b[l]
        #pragma unroll
        for (int j = 0; j < 8; ++j) {
            float4 b4 = sB[l * CN_F4 + j * 32 + lane];
            x[j].x = fmaf(in4[j].x, s, x[j].x) + b4.x;
            x[j].y = fmaf(in4[j].y, s, x[j].y) + b4.y;
            x[j].z = fmaf(in4[j].z, s, x[j].z) + b4.z;
            x[j].w = fmaf(in4[j].w, s, x[j].w) + b4.w;
        }
    }

    #pragma unroll
    for (int j = 0; j < 8; ++j) {
        rout[j * 32 + lane] = x[j];
    }
}

extern "C" void kernel_launch(void* const* d_in, const int* in_sizes, int n_in,
                              void* d_out, int out_size)
{
    const float* inp  = (const float*)d_in[0];   // [B, D]
    const float* W    = (const float*)d_in[1];   // [L, D]
    const float* bias = (const float*)d_in[2];   // [L, D]
    float* out        = (float*)d_out;           // [B, D]

    const int B = in_sizes[0] / CN_D;            // 16384
    const int blocks = B / CN_WARPS;             // 2048

    cross_network_kernel<<<blocks, CN_THREADS>>>(inp, W, bias, out);
}

// round 3
// speedup vs baseline: 1.3837x; 1.3837x over previous
#include <cuda_runtime.h>
#include <cuda_bf16.h>

// DCN-v1 cross network, closed form:
//   x_l = input * A_l + cumB_l   (A scalar per row, cumB row-independent)
//   d_l = dot(input, w_l)        (per row)
//   c_l = dot(cumB_l, w_l)       (row-independent constant)
//   s_l = A_l * d_l + c_l ;  A_{l+1} = A_l + s_l ;  cumB_{l+1} = cumB_l + b_l
//   out = input * A_6 + cumB_6
//
// Kernel 1 (1 block): compute c[6] and Bsum = cumB_6 into device globals.
// Kernel 2: per row, 6 simultaneous dots + scalar recurrence + scaled write.

#define CN_D       1024
#define CN_F4      256              // float4 per row
#define CN_L       6
#define CN_THREADS 256
#define CN_ROWS_PER_WARP 2
#define CN_ROWS_PER_BLOCK (8 * CN_ROWS_PER_WARP)   // 16

__device__ float  g_c[CN_L];
__device__ float4 g_bsum[CN_F4];

// ---------------------------------------------------------------------------
// Precompute c[l] = dot(cumB_l, w_l) and Bsum = sum_l b_l. One block, 256 thr.
// ---------------------------------------------------------------------------
__global__ void cn_precompute(const float* __restrict__ W,
                              const float* __restrict__ bias)
{
    __shared__ float sred[8][CN_L];

    const int tid  = threadIdx.x;        // 0..255, one float4 of D each
    const int lane = tid & 31;
    const int warp = tid >> 5;

    const float4* W4 = (const float4*)W;
    const float4* B4 = (const float4*)bias;

    float4 cum = make_float4(0.f, 0.f, 0.f, 0.f);
    float cpart[CN_L];

    #pragma unroll
    for (int l = 0; l < CN_L; ++l) {
        float4 w = W4[l * CN_F4 + tid];
        cpart[l] = cum.x * w.x + cum.y * w.y + cum.z * w.z + cum.w * w.w;
        float4 b = B4[l * CN_F4 + tid];
        cum.x += b.x; cum.y += b.y; cum.z += b.z; cum.w += b.w;
    }

    #pragma unroll
    for (int l = 0; l < CN_L; ++l) {
        float v = cpart[l];
        v += __shfl_xor_sync(0xFFFFFFFFu, v, 16);
        v += __shfl_xor_sync(0xFFFFFFFFu, v, 8);
        v += __shfl_xor_sync(0xFFFFFFFFu, v, 4);
        v += __shfl_xor_sync(0xFFFFFFFFu, v, 2);
        v += __shfl_xor_sync(0xFFFFFFFFu, v, 1);
        if (lane == 0) sred[warp][l] = v;
    }
    __syncthreads();

    if (warp == 0 && lane < CN_L) {
        float v = 0.f;
        #pragma unroll
        for (int w = 0; w < 8; ++w) v += sred[w][lane];
        g_c[lane] = v;
    }

    g_bsum[tid] = cum;
}

// ---------------------------------------------------------------------------
// Main kernel: 2 rows per warp, 16 rows per block.
// ---------------------------------------------------------------------------
__global__ __launch_bounds__(CN_THREADS, 2)
void cn_main(const float* __restrict__ inp,
             const float* __restrict__ W,
             float* __restrict__ out)
{
    __shared__ float4 sW[CN_L * CN_F4];   // 24 KB
    __shared__ float4 sBsum[CN_F4];       // 4 KB
    __shared__ float  sc[CN_L];

    const int tid  = threadIdx.x;
    const int lane = tid & 31;
    const int warp = tid >> 5;

    const size_t row0 = (size_t)blockIdx.x * CN_ROWS_PER_BLOCK
                      + (size_t)warp * CN_ROWS_PER_WARP;

    const float4* __restrict__ rinA = (const float4*)(inp + row0 * CN_D);
    const float4* __restrict__ rinB = (const float4*)(inp + (row0 + 1) * CN_D);

    // Front-batch the 16 input LDG.128s (independent of shared staging).
    float4 inA[8], inB[8];
    #pragma unroll
    for (int j = 0; j < 8; ++j) inA[j] = rinA[j * 32 + lane];
    #pragma unroll
    for (int j = 0; j < 8; ++j) inB[j] = rinB[j * 32 + lane];

    // Stage W, Bsum, c into shared.
    const float4* gW = (const float4*)W;
    #pragma unroll
    for (int i = 0; i < CN_L; ++i) sW[tid + i * CN_THREADS] = gW[tid + i * CN_THREADS];
    sBsum[tid] = g_bsum[tid];
    if (tid < CN_L) sc[tid] = g_c[tid];
    __syncthreads();

    // 12 simultaneous dot products (6 layers x 2 rows), single pass over x.
    float acc[2][CN_L];
    #pragma unroll
    for (int l = 0; l < CN_L; ++l) { acc[0][l] = 0.f; acc[1][l] = 0.f; }

    #pragma unroll
    for (int j = 0; j < 8; ++j) {
        #pragma unroll
        for (int l = 0; l < CN_L; ++l) {
            float4 w = sW[l * CN_F4 + j * 32 + lane];
            float a = acc[0][l];
            a = fmaf(inA[j].x, w.x, a);
            a = fmaf(inA[j].y, w.y, a);
            a = fmaf(inA[j].z, w.z, a);
            a = fmaf(inA[j].w, w.w, a);
            acc[0][l] = a;
            float b = acc[1][l];
            b = fmaf(inB[j].x, w.x, b);
            b = fmaf(inB[j].y, w.y, b);
            b = fmaf(inB[j].z, w.z, b);
            b = fmaf(inB[j].w, w.w, b);
            acc[1][l] = b;
        }
    }

    // Butterfly-reduce all 12 scalars (every lane ends with the full sum).
    #pragma unroll
    for (int r = 0; r < 2; ++r) {
        #pragma unroll
        for (int l = 0; l < CN_L; ++l) {
            float v = acc[r][l];
            v += __shfl_xor_sync(0xFFFFFFFFu, v, 16);
            v += __shfl_xor_sync(0xFFFFFFFFu, v, 8);
            v += __shfl_xor_sync(0xFFFFFFFFu, v, 4);
            v += __shfl_xor_sync(0xFFFFFFFFu, v, 2);
            v += __shfl_xor_sync(0xFFFFFFFFu, v, 1);
            acc[r][l] = v;
        }
    }

    // Scalar recurrence: A_{l+1} = A_l + (A_l * d_l + c_l)
    float A0 = 1.f, A1 = 1.f;
    #pragma unroll
    for (int l = 0; l < CN_L; ++l) {
        A0 += fmaf(A0, acc[0][l], sc[l]);
        A1 += fmaf(A1, acc[1][l], sc[l]);
    }

    // out = input * A + Bsum
    float4* __restrict__ routA = (float4*)(out + row0 * CN_D);
    float4* __restrict__ routB = (float4*)(out + (row0 + 1) * CN_D);
    #pragma unroll
    for (int j = 0; j < 8; ++j) {
        float4 bs = sBsum[j * 32 + lane];
        float4 oa, ob;
        oa.x = fmaf(inA[j].x, A0, bs.x);
        oa.y = fmaf(inA[j].y, A0, bs.y);
        oa.z = fmaf(inA[j].z, A0, bs.z);
        oa.w = fmaf(inA[j].w, A0, bs.w);
        ob.x = fmaf(inB[j].x, A1, bs.x);
        ob.y = fmaf(inB[j].y, A1, bs.y);
        ob.z = fmaf(inB[j].z, A1, bs.z);
        ob.w = fmaf(inB[j].w, A1, bs.w);
        routA[j * 32 + lane] = oa;
        routB[j * 32 + lane] = ob;
    }
}

extern "C" void kernel_launch(void* const* d_in, const int* in_sizes, int n_in,
                              void* d_out, int out_size)
{
    const float* inp  = (const float*)d_in[0];   // [B, D]
    const float* W    = (const float*)d_in[1];   // [L, D]
    const float* bias = (const float*)d_in[2];   // [L, D]
    float* out        = (float*)d_out;           // [B, D]

    const int B = in_sizes[0] / CN_D;                    // 16384
    const int blocks = B / CN_ROWS_PER_BLOCK;            // 1024

    cn_precompute<<<1, CN_THREADS>>>(W, bias);
    cn_main<<<blocks, CN_THREADS>>>(inp, W, out);
}